// round 16
// baseline (speedup 1.0000x reference)
#include <cuda_runtime.h>

// ---------------------------------------------------------------------------
// out[i, j] = f(j-1) - f(j),  f(j) = relu(1 - relu(x_full[j+1] - x_i) /
//                                         (x_full[j+1] - x_full[j] + 1e-9))
// sentinels f(-1)=1, f(n_full-1)=0; nonzeros only in j in [k-2, k+5].
// Single fused kernel, one warp per row (best measured fused shape):
//   prologue: interpolation-guess + direction-latched ballot search on
//             GLOBAL x_full (32 consecutive probes = 1-2 cache lines,
//             typically one round; no smem, no staging, no syncthreads)
//   body:     branch-free STG.128 zero of the whole row, then same-lane
//             patch of the <=3 window chunks (program-order overwrite).
// End-to-end write ceiling measured ~5.9 TB/s -> floor ~46us; this trims
// the prologue that kept R6 at 47.2.
// ---------------------------------------------------------------------------

__device__ __forceinline__ float evalf_g(const float* __restrict__ xf,
                                         int j, int n, float x) {
    if (j < 0) return 1.0f;
    if (j >= n - 1) return 0.0f;
    float xa = __ldg(xf + j);
    float xb = __ldg(xf + j + 1);
    float t  = fmaxf(0.f, xb - x);
    return fmaxf(0.f, 1.0f - t / (xb - xa + 1e-9f));
}

__device__ __forceinline__ float value_g(const float* __restrict__ xf,
                                         int c, int n, float x) {
    return evalf_g(xf, c - 1, n, x) - evalf_g(xf, c, n, x);
}

__global__ void __launch_bounds__(256)
fused_kernel(const float* __restrict__ x_eval,
             const float* __restrict__ x_full,
             float* __restrict__ out,
             int n_points, int n_full) {
    int gwarp = (blockIdx.x * blockDim.x + threadIdx.x) >> 5;
    int lane  = threadIdx.x & 31;
    if (gwarp >= n_points) return;

    float x = __ldg(x_eval + gwarp);
    int n = n_full;

    // ---- guess + direction-latched ballot search (validated R14/R15) -----
    const unsigned FULL = 0xffffffffu;
    int guess = (int)(x * (float)(n - 1));
    if (guess < 0) guess = 0;
    if (guess > n - 1) guess = n - 1;
    int base = guess - 15;
    int dir  = 0;
    int k0;
    while (true) {
        int m  = base + lane;
        int mc = m < 0 ? 0 : (m > n - 1 ? n - 1 : m);
        bool t = (m < 0) ? true
               : (m > n - 1) ? false
               : (__ldg(x_full + mc) <= x);
        unsigned b = __ballot_sync(FULL, t);
        if (b == FULL) {
            if (dir < 0)            { k0 = base + 31; break; }
            if (base + 31 >= n - 1) { k0 = n - 1;    break; }
            dir = 1;  base += 32;
        } else if (b == 0u) {
            if (dir > 0)  { k0 = base - 1; break; }
            if (base <= 0){ k0 = -1;       break; }
            dir = -1; base -= 32;
        } else {
            k0 = base + (31 - __clz(b));
            break;
        }
    }

    int k = k0 < 0 ? 0 : k0;
    if (k > n - 2) k = n - 2;
    int j0 = (k - 2 < 0) ? 0 : (k - 2);
    int j1 = (k + 5 > n - 1) ? (n - 1) : (k + 5);

    // ---- row layout: rows only 4B aligned (n_full odd) -------------------
    int rbase = gwarp * n;                      // < 2^31
    int head  = (-rbase) & 3;                   // scalars to 16B alignment
    if (head > n) head = n;
    int n_rem = n - head;
    int n4c   = n_rem >> 2;
    int tailc = n_rem & 3;
    float4* o4 = reinterpret_cast<float4*>(out + rbase + head);

    if (lane < head)                            // head: exact formula
        out[rbase + lane] = value_g(x_full, lane, n, x);

    // ---- branch-free zero of the whole row (the hot store stream) --------
    const float4 z = make_float4(0.f, 0.f, 0.f, 0.f);
    #pragma unroll 4
    for (int t = lane; t < n4c; t += 32)
        __stcs(o4 + t, z);

    if (lane < tailc) {                         // tail: exact formula
        int c = head + (n4c << 2) + lane;
        out[rbase + c] = value_g(x_full, c, n, x);
    }

    // ---- same-lane patch of the <=3 window chunks ------------------------
    int cl = (j0 > head) ? ((j0 - head) >> 2) : 0;
    int ch = (j1 >= head) ? ((j1 - head) >> 2) : -1;
    if (ch > n4c - 1) ch = n4c - 1;
    for (int wc = cl; wc <= ch; ++wc) {
        if ((int)(wc & 31) == lane) {
            int c = head + (wc << 2);
            float4 v;
            v.x = value_g(x_full, c,     n, x);
            v.y = value_g(x_full, c + 1, n, x);
            v.z = value_g(x_full, c + 2, n, x);
            v.w = value_g(x_full, c + 3, n, x);
            __stcs(o4 + wc, v);                 // overwrites own zero
        }
    }
}

extern "C" void kernel_launch(void* const* d_in, const int* in_sizes, int n_in,
                              void* d_out, int out_size) {
    const float* x_eval = (const float*)d_in[0];  // (n_points, 1) float32
    const float* x_full = (const float*)d_in[1];  // (n_full,)    float32 sorted
    float* out = (float*)d_out;                   // (n_points, n_full) float32

    int n_points = in_sizes[0];
    int n_full   = in_sizes[1];

    int threads = 256;                            // 8 rows per block
    int blocks  = (n_points * 32 + threads - 1) / threads;

    fused_kernel<<<blocks, threads>>>(x_eval, x_full, out, n_points, n_full);
}

// round 17
// speedup vs baseline: 1.0908x; 1.0908x over previous
#include <cuda_runtime.h>

// ---------------------------------------------------------------------------
// out[i, j] = f(j-1) - f(j),  f(j) = relu(1 - relu(x_full[j+1] - x_i) /
//                                         (x_full[j+1] - x_full[j] + 1e-9))
// sentinels f(-1)=1, f(n_full-1)=0; nonzeros only in j in [k-2, k+5].
// Proven-best structure (R6, 47.2us): warp-per-row, smem-staged knots,
// zero-spans before/after the window (no overwrite patch), window chunks
// with exact formula.  Single change vs R6: the 11-step dependent binary
// search -> interpolation-guess + direction-latched ballot search on smem
// (1-2 parallel probe rounds, validated R14-R16).
// ---------------------------------------------------------------------------

__device__ __forceinline__ float evalf_s(const float* __restrict__ sxf,
                                         int j, int n_full, float x) {
    if (j < 0) return 1.0f;
    if (j >= n_full - 1) return 0.0f;
    float xa = sxf[j];
    float xb = sxf[j + 1];
    float t  = fmaxf(0.f, xb - x);
    return fmaxf(0.f, 1.0f - t / (xb - xa + 1e-9f));
}

__device__ __forceinline__ float value_s(const float* __restrict__ sxf,
                                         int c, int n_full, float x) {
    return evalf_s(sxf, c - 1, n_full, x) - evalf_s(sxf, c, n_full, x);
}

__global__ void __launch_bounds__(256)
fused_kernel(const float* __restrict__ x_eval,
             const float* __restrict__ x_full,
             float* __restrict__ out,
             int n_points, int n_full) {
    extern __shared__ float sxf[];                 // n_full floats (8.2 KB)
    for (int m = threadIdx.x; m < n_full; m += blockDim.x)
        sxf[m] = x_full[m];
    __syncthreads();

    int gwarp = (blockIdx.x * blockDim.x + threadIdx.x) >> 5;
    int lane  = threadIdx.x & 31;
    if (gwarp >= n_points) return;
    float x = __ldg(x_eval + gwarp);               // warp-uniform
    int n = n_full;

    // ---- guess + direction-latched ballot search on smem -----------------
    const unsigned FULL = 0xffffffffu;
    int guess = (int)(x * (float)(n - 1));
    if (guess < 0) guess = 0;
    if (guess > n - 1) guess = n - 1;
    int base = guess - 15;
    int dir  = 0;
    int k0;
    while (true) {
        int m  = base + lane;
        bool t = (m < 0) ? true
               : (m > n - 1) ? false
               : (sxf[m] <= x);
        unsigned b = __ballot_sync(FULL, t);
        if (b == FULL) {
            if (dir < 0)            { k0 = base + 31; break; }
            if (base + 31 >= n - 1) { k0 = n - 1;    break; }
            dir = 1;  base += 32;
        } else if (b == 0u) {
            if (dir > 0)  { k0 = base - 1; break; }
            if (base <= 0){ k0 = -1;       break; }
            dir = -1; base -= 32;
        } else {
            k0 = base + (31 - __clz(b));
            break;
        }
    }

    int k = k0 < 0 ? 0 : k0;
    if (k > n - 2) k = n - 2;
    int j0 = (k - 2 < 0) ? 0 : (k - 2);
    int j1 = (k + 5 > n - 1) ? (n - 1) : (k + 5);

    // ---- row layout (rows only 4B aligned: n_full odd) -------------------
    int rbase = gwarp * n;                         // < 2^31
    int head  = (-rbase) & 3;                      // scalars to 16B align
    if (head > n) head = n;

    if (lane < head)                               // head: exact formula
        out[rbase + lane] = value_s(sxf, lane, n, x);

    int n_rem = n - head;
    int n4c   = n_rem >> 2;
    int tailc = n_rem & 3;
    float4* o4 = reinterpret_cast<float4*>(out + rbase + head);

    // float4-chunk span touching the window (warp-uniform, <=3 chunks)
    int a    = j0 - head;
    int w_lo = (a <= 0) ? 0 : (a >> 2);
    int w_hi = (j1 - head) >> 2;
    if (w_hi > n4c - 1) w_hi = n4c - 1;
    if (w_hi < w_lo)    w_hi = w_lo;

    const float4 z = make_float4(0.f, 0.f, 0.f, 0.f);

    // zero span before window: branch-free pure store stream
    #pragma unroll 4
    for (int t = lane; t < w_lo; t += 32)
        __stcs(o4 + t, z);

    // zero span after window
    #pragma unroll 4
    for (int t = w_hi + 1 + lane; t < n4c; t += 32)
        __stcs(o4 + t, z);

    // window chunks: one per lane, exact formula
    int wc = w_lo + lane;
    if (wc <= w_hi) {
        int c = head + (wc << 2);
        float4 v;
        v.x = value_s(sxf, c,     n, x);
        v.y = value_s(sxf, c + 1, n, x);
        v.z = value_s(sxf, c + 2, n, x);
        v.w = value_s(sxf, c + 3, n, x);
        __stcs(o4 + wc, v);
    }

    // tail scalars (<=3): exact formula
    if (lane < tailc) {
        int c = head + (n4c << 2) + lane;
        out[rbase + c] = value_s(sxf, c, n, x);
    }
}

extern "C" void kernel_launch(void* const* d_in, const int* in_sizes, int n_in,
                              void* d_out, int out_size) {
    const float* x_eval = (const float*)d_in[0];  // (n_points, 1) float32
    const float* x_full = (const float*)d_in[1];  // (n_full,)    float32 sorted
    float* out = (float*)d_out;                   // (n_points, n_full) float32

    int n_points = in_sizes[0];
    int n_full   = in_sizes[1];

    int threads = 256;                            // 8 rows per block
    int warps_per_block = threads / 32;
    int blocks = (n_points + warps_per_block - 1) / warps_per_block;
    size_t smem = (size_t)n_full * sizeof(float);

    fused_kernel<<<blocks, threads, smem>>>(x_eval, x_full, out,
                                            n_points, n_full);
}